// round 5
// baseline (speedup 1.0000x reference)
#include <cuda_runtime.h>

#define N_    1024
#define M_    1024
#define D_    128
#define NNZ_  32768
#define H_    256

typedef unsigned long long u64;

// ---------------- device scratch (no allocations allowed) ----------------
__device__ int   g_cnt[M_];
__device__ __align__(16) float g_sum[M_ * D_];     // raw scatter sums [m][d]
__device__ __align__(16) float g_hxT[H_ * N_];     // [h][n]
__device__ __align__(16) float g_hebT[H_ * M_];    // [h][m]  (includes /cnt and +b1)

// ---------------- small helpers ----------------
__device__ __forceinline__ u64 bcast2(float v) {
    u64 r;
    asm("mov.b64 %0, {%1, %1};" : "=l"(r) : "f"(v));
    return r;
}

__device__ __forceinline__ float2 unpack2(u64 v) {
    float lo, hi;
    asm("mov.b64 {%0, %1}, %2;" : "=f"(lo), "=f"(hi) : "l"(v));
    return make_float2(lo, hi);
}

// acc2 += relu(a2 + b2) * w2   (packed f32x2; relu on the scalar halves)
__device__ __forceinline__ void relu_fma2(u64 &acc, u64 a, u64 b, u64 w) {
    asm("{\n\t"
        ".reg .b64 t;\n\t"
        ".reg .f32 lo, hi;\n\t"
        "add.rn.f32x2 t, %1, %2;\n\t"
        "mov.b64 {lo, hi}, t;\n\t"
        "max.f32 lo, lo, 0f00000000;\n\t"
        "max.f32 hi, hi, 0f00000000;\n\t"
        "mov.b64 t, {lo, hi};\n\t"
        "fma.rn.f32x2 %0, t, %3, %0;\n\t"
        "}"
        : "+l"(acc) : "l"(a), "l"(b), "l"(w));
}

__device__ __forceinline__ float sigmoidf_fast(float x) {
    return 1.0f / (1.0f + __expf(-x));
}

// ---------------- stage 1: zero logits (d_out) + scratch ----------------
__global__ void k_init(float* __restrict__ out) {
    int i = blockIdx.x * blockDim.x + threadIdx.x;
    float4 z = make_float4(0.f, 0.f, 0.f, 0.f);
    ((float4*)out)[i] = z;
    if (i < (M_ * D_) / 4) ((float4*)g_sum)[i] = z;
    if (i < M_) g_cnt[i] = 0;
}

// ---------------- stage 2: vector-atomic scatter ----------------
__global__ __launch_bounds__(256) void k_scatter(const float* __restrict__ X,
                                                 const int* __restrict__ V,
                                                 const int* __restrict__ E) {
    int edge = blockIdx.x * 8 + (threadIdx.x >> 5);
    int lane = threadIdx.x & 31;
    int e = E[edge];
    int v = V[edge];
    float4 x = *(const float4*)&X[v * D_ + lane * 4];
    float* dst = &g_sum[e * D_ + lane * 4];
    asm volatile("red.global.add.v4.f32 [%0], {%1, %2, %3, %4};"
                 :: "l"(dst), "f"(x.x), "f"(x.y), "f"(x.z), "f"(x.w) : "memory");
    if (lane == 0) atomicAdd(&g_cnt[e], 1);
}

// ---------------- stage 3: the two small GEMMs (fused, transposed output) --
__global__ __launch_bounds__(256) void k_gemm(const float* __restrict__ X,
                                              const float* __restrict__ W1,
                                              const float* __restrict__ b1) {
    int z = blockIdx.z;
    const float* A    = z ? g_sum  : X;
    float*       outT = z ? g_hebT : g_hxT;
    int dof = z ? D_ : 0;

    int n0 = blockIdx.x * 64;
    int h0 = blockIdx.y * 64;

    __shared__ float As[16][65];   // [dk][n]
    __shared__ float Ws[16][64];   // [dk][h]

    int tid = threadIdx.x;
    int tn  = tid & 15;
    int th  = tid >> 4;

    float acc[4][4];
    #pragma unroll
    for (int i = 0; i < 4; i++)
        #pragma unroll
        for (int j = 0; j < 4; j++)
            acc[i][j] = 0.f;

    for (int d0 = 0; d0 < D_; d0 += 16) {
        #pragma unroll
        for (int r = 0; r < 4; r++) {
            int i  = r * 256 + tid;
            int dk = i & 15;
            int nl = i >> 4;
            As[dk][nl] = A[(n0 + nl) * D_ + d0 + dk];
        }
        #pragma unroll
        for (int r = 0; r < 4; r++) {
            int i  = r * 256 + tid;
            int hh = i & 63;
            int dk = i >> 6;
            Ws[dk][hh] = W1[(dof + d0 + dk) * H_ + h0 + hh];
        }
        __syncthreads();
        #pragma unroll
        for (int dk = 0; dk < 16; dk++) {
            float a[4], w[4];
            #pragma unroll
            for (int i = 0; i < 4; i++) a[i] = As[dk][tn * 4 + i];
            #pragma unroll
            for (int j = 0; j < 4; j++) w[j] = Ws[dk][th * 4 + j];
            #pragma unroll
            for (int i = 0; i < 4; i++)
                #pragma unroll
                for (int j = 0; j < 4; j++)
                    acc[i][j] = fmaf(a[i], w[j], acc[i][j]);
        }
        __syncthreads();
    }

    float scale[4] = {1.f, 1.f, 1.f, 1.f};
    if (z) {
        #pragma unroll
        for (int i = 0; i < 4; i++) {
            int c = g_cnt[n0 + tn * 4 + i];
            scale[i] = 1.0f / ((c > 0) ? (float)c : 1.0f);
        }
    }
    #pragma unroll
    for (int j = 0; j < 4; j++) {
        int h = h0 + th * 4 + j;
        float bb = z ? b1[h] : 0.f;
        float4 v = make_float4(acc[0][j] * scale[0] + bb,
                               acc[1][j] * scale[1] + bb,
                               acc[2][j] * scale[2] + bb,
                               acc[3][j] * scale[3] + bb);
        *(float4*)&outT[h * N_ + n0 + tn * 4] = v;
    }
}

// ---------------- stage 4: main N x M x H contraction (h-split) ----------
// grid (H/64, M/64, N/64) = 1024 blocks, 128 threads, 8 blocks/SM resident.
// hx tile stored pre-duplicated as f32x2 pairs -> zero broadcast MOVs inner.
__global__ __launch_bounds__(128, 8) void k_main(const float* __restrict__ W2,
                                                 float* __restrict__ out) {
    __shared__ __align__(16) u64   hxd[32][66];    // [h][n] duplicated {v,v}
    __shared__ __align__(16) float heb_s[32][68];  // [h][m]
    __shared__ __align__(16) u64   w2d[32];        // duplicated {w,w}

    int hb = blockIdx.x * 64;
    int m0 = blockIdx.y * 64;
    int n0 = blockIdx.z * 64;
    int tid = threadIdx.x;
    int tn  = tid & 15;   // n base = tn*4
    int tm  = tid >> 4;   // m base = tm*8

    u64 acc[4][4];        // [ni][mpair]
    #pragma unroll
    for (int i = 0; i < 4; i++)
        #pragma unroll
        for (int p = 0; p < 4; p++)
            acc[i][p] = 0ull;

    int cg = tid & 15;    // float4 column group for loads
    int r0 = tid >> 4;    // row base for loads (0..7)

    for (int sc = 0; sc < 2; sc++) {
        int hbase = hb + sc * 32;
        #pragma unroll
        for (int k = 0; k < 4; k++) {
            int hh = k * 8 + r0;
            float4 a = *(const float4*)&g_hxT[(hbase + hh) * N_ + n0 + cg * 4];
            ulonglong2 p0, p1;
            p0.x = bcast2(a.x); p0.y = bcast2(a.y);
            p1.x = bcast2(a.z); p1.y = bcast2(a.w);
            *(ulonglong2*)&hxd[hh][cg * 4]     = p0;
            *(ulonglong2*)&hxd[hh][cg * 4 + 2] = p1;
            *(float4*)&heb_s[hh][cg * 4] = *(const float4*)&g_hebT[(hbase + hh) * M_ + m0 + cg * 4];
        }
        if (tid < 32) w2d[tid] = bcast2(W2[hbase + tid]);
        __syncthreads();

        #pragma unroll 4
        for (int hh = 0; hh < 32; hh++) {
            ulonglong2 q01 = *(const ulonglong2*)&hxd[hh][tn * 4];
            ulonglong2 q23 = *(const ulonglong2*)&hxd[hh][tn * 4 + 2];
            ulonglong2 e0  = *(const ulonglong2*)&heb_s[hh][tm * 8];
            ulonglong2 e1  = *(const ulonglong2*)&heb_s[hh][tm * 8 + 4];
            u64 w2p = w2d[hh];

            relu_fma2(acc[0][0], e0.x, q01.x, w2p);
            relu_fma2(acc[0][1], e0.y, q01.x, w2p);
            relu_fma2(acc[0][2], e1.x, q01.x, w2p);
            relu_fma2(acc[0][3], e1.y, q01.x, w2p);

            relu_fma2(acc[1][0], e0.x, q01.y, w2p);
            relu_fma2(acc[1][1], e0.y, q01.y, w2p);
            relu_fma2(acc[1][2], e1.x, q01.y, w2p);
            relu_fma2(acc[1][3], e1.y, q01.y, w2p);

            relu_fma2(acc[2][0], e0.x, q23.x, w2p);
            relu_fma2(acc[2][1], e0.y, q23.x, w2p);
            relu_fma2(acc[2][2], e1.x, q23.x, w2p);
            relu_fma2(acc[2][3], e1.y, q23.x, w2p);

            relu_fma2(acc[3][0], e0.x, q23.y, w2p);
            relu_fma2(acc[3][1], e0.y, q23.y, w2p);
            relu_fma2(acc[3][2], e1.x, q23.y, w2p);
            relu_fma2(acc[3][3], e1.y, q23.y, w2p);
        }
        __syncthreads();
    }

    // epilogue: vector-RED partial logits into out[n][m]
    #pragma unroll
    for (int i = 0; i < 4; i++) {
        int n = n0 + tn * 4 + i;
        float2 a = unpack2(acc[i][0]);
        float2 b = unpack2(acc[i][1]);
        float2 c = unpack2(acc[i][2]);
        float2 d = unpack2(acc[i][3]);
        float* dst = &out[n * M_ + m0 + tm * 8];
        asm volatile("red.global.add.v4.f32 [%0], {%1, %2, %3, %4};"
                     :: "l"(dst), "f"(a.x), "f"(a.y), "f"(b.x), "f"(b.y) : "memory");
        asm volatile("red.global.add.v4.f32 [%0], {%1, %2, %3, %4};"
                     :: "l"(dst + 4), "f"(c.x), "f"(c.y), "f"(d.x), "f"(d.y) : "memory");
    }
}

// ---------------- stage 5: sigmoid epilogue (in place on d_out) ----------
__global__ void k_sig(float* __restrict__ out, const float* __restrict__ b2p) {
    int i = blockIdx.x * blockDim.x + threadIdx.x;
    float b2 = b2p[0];
    float4 v = ((float4*)out)[i];
    v.x = sigmoidf_fast(v.x + b2);
    v.y = sigmoidf_fast(v.y + b2);
    v.z = sigmoidf_fast(v.z + b2);
    v.w = sigmoidf_fast(v.w + b2);
    ((float4*)out)[i] = v;
}

// ---------------- launch ----------------
extern "C" void kernel_launch(void* const* d_in, const int* in_sizes, int n_in,
                              void* d_out, int out_size) {
    const float* X  = (const float*)d_in[0];
    const int*   V  = (const int*)d_in[1];
    const int*   E  = (const int*)d_in[2];
    const float* W1 = (const float*)d_in[3];
    const float* b1 = (const float*)d_in[4];
    const float* W2 = (const float*)d_in[5];
    const float* b2 = (const float*)d_in[6];
    float* out = (float*)d_out;

    k_init<<<1024, 256>>>(out);
    k_scatter<<<NNZ_ / 8, 256>>>(X, V, E);
    k_gemm<<<dim3(N_ / 64, H_ / 64, 2), 256>>>(X, W1, b1);
    k_main<<<dim3(H_ / 64, M_ / 64, N_ / 64), 128>>>(W2, out);
    k_sig<<<1024, 256>>>(out, b2);
}

// round 6
// speedup vs baseline: 1.0407x; 1.0407x over previous
#include <cuda_runtime.h>

#define N_    1024
#define M_    1024
#define D_    128
#define NNZ_  32768
#define H_    256

typedef unsigned long long u64;

// ---------------- device scratch (no allocations allowed) ----------------
__device__ int      g_cnt[M_];
__device__ unsigned g_ticket[256];                 // per 64x64 output tile
__device__ __align__(16) float g_sum[M_ * D_];     // raw scatter sums [m][d]
__device__ __align__(16) float g_hxT[H_ * N_];     // [h][n]
__device__ __align__(16) float g_hebT[H_ * M_];    // [h][m]  (includes /cnt and +b1)

// ---------------- small helpers ----------------
__device__ __forceinline__ u64 bcast2(float v) {
    u64 r;
    asm("mov.b64 %0, {%1, %1};" : "=l"(r) : "f"(v));
    return r;
}

__device__ __forceinline__ float2 unpack2(u64 v) {
    float lo, hi;
    asm("mov.b64 {%0, %1}, %2;" : "=f"(lo), "=f"(hi) : "l"(v));
    return make_float2(lo, hi);
}

// acc2 += relu(a2 + b2) * w2   (packed f32x2; relu on the scalar halves)
__device__ __forceinline__ void relu_fma2(u64 &acc, u64 a, u64 b, u64 w) {
    asm("{\n\t"
        ".reg .b64 t;\n\t"
        ".reg .f32 lo, hi;\n\t"
        "add.rn.f32x2 t, %1, %2;\n\t"
        "mov.b64 {lo, hi}, t;\n\t"
        "max.f32 lo, lo, 0f00000000;\n\t"
        "max.f32 hi, hi, 0f00000000;\n\t"
        "mov.b64 t, {lo, hi};\n\t"
        "fma.rn.f32x2 %0, t, %3, %0;\n\t"
        "}"
        : "+l"(acc) : "l"(a), "l"(b), "l"(w));
}

__device__ __forceinline__ float sigmoidf_fast(float x) {
    return 1.0f / (1.0f + __expf(-x));
}

// ---------------- stage 1: zero logits (d_out) + scratch ----------------
__global__ void k_init(float* __restrict__ out) {
    int i = blockIdx.x * blockDim.x + threadIdx.x;
    float4 z = make_float4(0.f, 0.f, 0.f, 0.f);
    ((float4*)out)[i] = z;
    if (i < (M_ * D_) / 4) ((float4*)g_sum)[i] = z;
    if (i < M_) g_cnt[i] = 0;
    if (i < 256) g_ticket[i] = 0;
}

// ---------------- stage 2: vector-atomic scatter ----------------
__global__ __launch_bounds__(256) void k_scatter(const float* __restrict__ X,
                                                 const int* __restrict__ V,
                                                 const int* __restrict__ E) {
    int edge = blockIdx.x * 8 + (threadIdx.x >> 5);
    int lane = threadIdx.x & 31;
    int e = E[edge];
    int v = V[edge];
    float4 x = *(const float4*)&X[v * D_ + lane * 4];
    float* dst = &g_sum[e * D_ + lane * 4];
    asm volatile("red.global.add.v4.f32 [%0], {%1, %2, %3, %4};"
                 :: "l"(dst), "f"(x.x), "f"(x.y), "f"(x.z), "f"(x.w) : "memory");
    if (lane == 0) atomicAdd(&g_cnt[e], 1);
}

// ---------------- stage 3: the two small GEMMs (fused, transposed output) --
__global__ __launch_bounds__(256) void k_gemm(const float* __restrict__ X,
                                              const float* __restrict__ W1,
                                              const float* __restrict__ b1) {
    int z = blockIdx.z;
    const float* A    = z ? g_sum  : X;
    float*       outT = z ? g_hebT : g_hxT;
    int dof = z ? D_ : 0;

    int n0 = blockIdx.x * 64;
    int h0 = blockIdx.y * 64;

    __shared__ float As[16][65];   // [dk][n]
    __shared__ float Ws[16][64];   // [dk][h]

    int tid = threadIdx.x;
    int tn  = tid & 15;
    int th  = tid >> 4;

    float acc[4][4];
    #pragma unroll
    for (int i = 0; i < 4; i++)
        #pragma unroll
        for (int j = 0; j < 4; j++)
            acc[i][j] = 0.f;

    for (int d0 = 0; d0 < D_; d0 += 16) {
        #pragma unroll
        for (int r = 0; r < 4; r++) {
            int i  = r * 256 + tid;
            int dk = i & 15;
            int nl = i >> 4;
            As[dk][nl] = A[(n0 + nl) * D_ + d0 + dk];
        }
        #pragma unroll
        for (int r = 0; r < 4; r++) {
            int i  = r * 256 + tid;
            int hh = i & 63;
            int dk = i >> 6;
            Ws[dk][hh] = W1[(dof + d0 + dk) * H_ + h0 + hh];
        }
        __syncthreads();
        #pragma unroll
        for (int dk = 0; dk < 16; dk++) {
            float a[4], w[4];
            #pragma unroll
            for (int i = 0; i < 4; i++) a[i] = As[dk][tn * 4 + i];
            #pragma unroll
            for (int j = 0; j < 4; j++) w[j] = Ws[dk][th * 4 + j];
            #pragma unroll
            for (int i = 0; i < 4; i++)
                #pragma unroll
                for (int j = 0; j < 4; j++)
                    acc[i][j] = fmaf(a[i], w[j], acc[i][j]);
        }
        __syncthreads();
    }

    float scale[4] = {1.f, 1.f, 1.f, 1.f};
    if (z) {
        #pragma unroll
        for (int i = 0; i < 4; i++) {
            int c = g_cnt[n0 + tn * 4 + i];
            scale[i] = 1.0f / ((c > 0) ? (float)c : 1.0f);
        }
    }
    #pragma unroll
    for (int j = 0; j < 4; j++) {
        int h = h0 + th * 4 + j;
        float bb = z ? b1[h] : 0.f;
        float4 v = make_float4(acc[0][j] * scale[0] + bb,
                               acc[1][j] * scale[1] + bb,
                               acc[2][j] * scale[2] + bb,
                               acc[3][j] * scale[3] + bb);
        *(float4*)&outT[h * N_ + n0 + tn * 4] = v;
    }
}

// ---------------- stage 4: main N x M x H contraction (h-split) ----------
// grid (H/64, M/64, N/64) = 1024 blocks, 128 threads, all co-resident.
// R3 inner loop (register broadcast). Last h-block per tile applies sigmoid.
__global__ __launch_bounds__(128, 7) void k_main(const float* __restrict__ W2,
                                                 const float* __restrict__ b2p,
                                                 float* __restrict__ out) {
    __shared__ __align__(16) float hx_s[32][64];
    __shared__ __align__(16) float heb_s[32][64];
    __shared__ float w2_s[64];
    __shared__ int   s_last;

    int hb = blockIdx.x * 64;
    int m0 = blockIdx.y * 64;
    int n0 = blockIdx.z * 64;
    int tid = threadIdx.x;
    int tn  = tid & 15;   // n base = tn*4
    int tm  = tid >> 4;   // m base = tm*8

    u64 acc[4][4];        // [ni][mpair]
    #pragma unroll
    for (int i = 0; i < 4; i++)
        #pragma unroll
        for (int p = 0; p < 4; p++)
            acc[i][p] = 0ull;

    if (tid < 64) w2_s[tid] = W2[hb + tid];

    int cg = tid & 15;    // float4 column group for loads
    int r0 = tid >> 4;    // row base for loads (0..7)

    for (int sc = 0; sc < 2; sc++) {
        int hbase = hb + sc * 32;
        #pragma unroll
        for (int k = 0; k < 4; k++) {
            int hh = k * 8 + r0;
            *(float4*)&hx_s[hh][cg * 4]  = *(const float4*)&g_hxT[(hbase + hh) * N_ + n0 + cg * 4];
            *(float4*)&heb_s[hh][cg * 4] = *(const float4*)&g_hebT[(hbase + hh) * M_ + m0 + cg * 4];
        }
        __syncthreads();

        #pragma unroll 8
        for (int hh = 0; hh < 32; hh++) {
            float4 hx4 = *(const float4*)&hx_s[hh][tn * 4];
            ulonglong2 e0 = *(const ulonglong2*)&heb_s[hh][tm * 8];
            ulonglong2 e1 = *(const ulonglong2*)&heb_s[hh][tm * 8 + 4];
            u64 w2p = bcast2(w2_s[sc * 32 + hh]);
            u64 q0 = bcast2(hx4.x);
            u64 q1 = bcast2(hx4.y);
            u64 q2 = bcast2(hx4.z);
            u64 q3 = bcast2(hx4.w);

            relu_fma2(acc[0][0], e0.x, q0, w2p);
            relu_fma2(acc[0][1], e0.y, q0, w2p);
            relu_fma2(acc[0][2], e1.x, q0, w2p);
            relu_fma2(acc[0][3], e1.y, q0, w2p);

            relu_fma2(acc[1][0], e0.x, q1, w2p);
            relu_fma2(acc[1][1], e0.y, q1, w2p);
            relu_fma2(acc[1][2], e1.x, q1, w2p);
            relu_fma2(acc[1][3], e1.y, q1, w2p);

            relu_fma2(acc[2][0], e0.x, q2, w2p);
            relu_fma2(acc[2][1], e0.y, q2, w2p);
            relu_fma2(acc[2][2], e1.x, q2, w2p);
            relu_fma2(acc[2][3], e1.y, q2, w2p);

            relu_fma2(acc[3][0], e0.x, q3, w2p);
            relu_fma2(acc[3][1], e0.y, q3, w2p);
            relu_fma2(acc[3][2], e1.x, q3, w2p);
            relu_fma2(acc[3][3], e1.y, q3, w2p);
        }
        __syncthreads();
    }

    // epilogue: vector-RED partial logits into out[n][m]
    #pragma unroll
    for (int i = 0; i < 4; i++) {
        int n = n0 + tn * 4 + i;
        float2 a = unpack2(acc[i][0]);
        float2 b = unpack2(acc[i][1]);
        float2 c = unpack2(acc[i][2]);
        float2 d = unpack2(acc[i][3]);
        float* dst = &out[n * M_ + m0 + tm * 8];
        asm volatile("red.global.add.v4.f32 [%0], {%1, %2, %3, %4};"
                     :: "l"(dst), "f"(a.x), "f"(a.y), "f"(b.x), "f"(b.y) : "memory");
        asm volatile("red.global.add.v4.f32 [%0], {%1, %2, %3, %4};"
                     :: "l"(dst + 4), "f"(c.x), "f"(c.y), "f"(d.x), "f"(d.y) : "memory");
    }

    // ticket: the 4th h-block to finish this (n,m) tile applies b2+sigmoid
    __threadfence();
    __syncthreads();
    if (tid == 0) {
        unsigned t = atomicAdd(&g_ticket[blockIdx.z * 16 + blockIdx.y], 1u);
        s_last = (t == 3u);
    }
    __syncthreads();
    if (s_last) {
        float b2v = __ldg(b2p);
        #pragma unroll
        for (int k = 0; k < 8; k++) {
            int n = n0 + k * 8 + r0;
            float* p = &out[n * M_ + m0 + cg * 4];
            float4 v;
            asm volatile("ld.global.cg.v4.f32 {%0,%1,%2,%3}, [%4];"
                         : "=f"(v.x), "=f"(v.y), "=f"(v.z), "=f"(v.w) : "l"(p));
            v.x = sigmoidf_fast(v.x + b2v);
            v.y = sigmoidf_fast(v.y + b2v);
            v.z = sigmoidf_fast(v.z + b2v);
            v.w = sigmoidf_fast(v.w + b2v);
            asm volatile("st.global.cg.v4.f32 [%0], {%1,%2,%3,%4};"
                         :: "l"(p), "f"(v.x), "f"(v.y), "f"(v.z), "f"(v.w) : "memory");
        }
    }
}

// ---------------- launch ----------------
extern "C" void kernel_launch(void* const* d_in, const int* in_sizes, int n_in,
                              void* d_out, int out_size) {
    const float* X  = (const float*)d_in[0];
    const int*   V  = (const int*)d_in[1];
    const int*   E  = (const int*)d_in[2];
    const float* W1 = (const float*)d_in[3];
    const float* b1 = (const float*)d_in[4];
    const float* W2 = (const float*)d_in[5];
    const float* b2 = (const float*)d_in[6];
    float* out = (float*)d_out;

    k_init<<<1024, 256>>>(out);
    k_scatter<<<NNZ_ / 8, 256>>>(X, V, E);
    k_gemm<<<dim3(N_ / 64, H_ / 64, 2), 256>>>(X, W1, b1);
    k_main<<<dim3(H_ / 64, M_ / 64, N_ / 64), 128>>>(W2, b2, out);
}

// round 7
// speedup vs baseline: 1.0752x; 1.0332x over previous
#include <cuda_runtime.h>

#define N_    1024
#define M_    1024
#define D_    128
#define NNZ_  32768
#define H_    256

typedef unsigned long long u64;

// ---------------- device scratch (no allocations allowed) ----------------
// NOTE: zero-initialized at module load; k_sig restores the zero state for
// g_sum / g_cnt after each invocation, so every call sees zeroed scratch.
__device__ int   g_cnt[M_];
__device__ __align__(16) float g_sum[M_ * D_];     // raw scatter sums [m][d]
__device__ __align__(16) float g_hxT[H_ * N_];     // [h][n]
__device__ __align__(16) float g_hebT[H_ * M_];    // [h][m]  (includes /cnt and +b1)

// ---------------- PDL helpers ----------------
__device__ __forceinline__ void pdl_wait() {
    asm volatile("griddepcontrol.wait;" ::: "memory");
}
__device__ __forceinline__ void pdl_trigger() {
    asm volatile("griddepcontrol.launch_dependents;" ::: "memory");
}

// ---------------- small helpers ----------------
__device__ __forceinline__ u64 bcast2(float v) {
    u64 r;
    asm("mov.b64 %0, {%1, %1};" : "=l"(r) : "f"(v));
    return r;
}

__device__ __forceinline__ float2 unpack2(u64 v) {
    float lo, hi;
    asm("mov.b64 {%0, %1}, %2;" : "=f"(lo), "=f"(hi) : "l"(v));
    return make_float2(lo, hi);
}

// acc2 += relu(a2 + b2) * w2   (packed f32x2; relu on the scalar halves)
__device__ __forceinline__ void relu_fma2(u64 &acc, u64 a, u64 b, u64 w) {
    asm("{\n\t"
        ".reg .b64 t;\n\t"
        ".reg .f32 lo, hi;\n\t"
        "add.rn.f32x2 t, %1, %2;\n\t"
        "mov.b64 {lo, hi}, t;\n\t"
        "max.f32 lo, lo, 0f00000000;\n\t"
        "max.f32 hi, hi, 0f00000000;\n\t"
        "mov.b64 t, {lo, hi};\n\t"
        "fma.rn.f32x2 %0, t, %3, %0;\n\t"
        "}"
        : "+l"(acc) : "l"(a), "l"(b), "l"(w));
}

__device__ __forceinline__ float sigmoidf_fast(float x) {
    return 1.0f / (1.0f + __expf(-x));
}

// ---------------- stage 1: scatter (+ zero d_out in extra blocks) --------
// blocks [0,1024): zero d_out. blocks [1024,5120): one warp per edge.
__global__ __launch_bounds__(256) void k_scatter(const float* __restrict__ X,
                                                 const int* __restrict__ V,
                                                 const int* __restrict__ E,
                                                 float* __restrict__ out) {
    int bx = blockIdx.x;
    if (bx < 1024) {
        int i = bx * 256 + threadIdx.x;
        ((float4*)out)[i] = make_float4(0.f, 0.f, 0.f, 0.f);
        pdl_trigger();
        return;
    }
    int edge = (bx - 1024) * 8 + (threadIdx.x >> 5);
    int lane = threadIdx.x & 31;
    int e = E[edge];
    int v = V[edge];
    float4 x = *(const float4*)&X[v * D_ + lane * 4];
    float* dst = &g_sum[e * D_ + lane * 4];
    asm volatile("red.global.add.v4.f32 [%0], {%1, %2, %3, %4};"
                 :: "l"(dst), "f"(x.x), "f"(x.y), "f"(x.z), "f"(x.w) : "memory");
    if (lane == 0) atomicAdd(&g_cnt[e], 1);
    pdl_trigger();
}

// ---------------- stage 2: the two small GEMMs (fused, transposed output) --
// z==0: outT = (X @ W1[:D]).T              (independent of scatter: NO wait)
// z==1: outT = ((g_sum @ W1[D:])*rcp).T+b1 (waits on scatter via PDL)
__global__ __launch_bounds__(256) void k_gemm(const float* __restrict__ X,
                                              const float* __restrict__ W1,
                                              const float* __restrict__ b1) {
    int z = blockIdx.z;
    if (z) pdl_wait();
    const float* A    = z ? g_sum  : X;
    float*       outT = z ? g_hebT : g_hxT;
    int dof = z ? D_ : 0;

    int n0 = blockIdx.x * 64;
    int h0 = blockIdx.y * 64;

    __shared__ float As[16][65];   // [dk][n]
    __shared__ float Ws[16][64];   // [dk][h]

    int tid = threadIdx.x;
    int tn  = tid & 15;
    int th  = tid >> 4;

    float acc[4][4];
    #pragma unroll
    for (int i = 0; i < 4; i++)
        #pragma unroll
        for (int j = 0; j < 4; j++)
            acc[i][j] = 0.f;

    for (int d0 = 0; d0 < D_; d0 += 16) {
        #pragma unroll
        for (int r = 0; r < 4; r++) {
            int i  = r * 256 + tid;
            int dk = i & 15;
            int nl = i >> 4;
            As[dk][nl] = A[(n0 + nl) * D_ + d0 + dk];
        }
        #pragma unroll
        for (int r = 0; r < 4; r++) {
            int i  = r * 256 + tid;
            int hh = i & 63;
            int dk = i >> 6;
            Ws[dk][hh] = W1[(dof + d0 + dk) * H_ + h0 + hh];
        }
        __syncthreads();
        #pragma unroll
        for (int dk = 0; dk < 16; dk++) {
            float a[4], w[4];
            #pragma unroll
            for (int i = 0; i < 4; i++) a[i] = As[dk][tn * 4 + i];
            #pragma unroll
            for (int j = 0; j < 4; j++) w[j] = Ws[dk][th * 4 + j];
            #pragma unroll
            for (int i = 0; i < 4; i++)
                #pragma unroll
                for (int j = 0; j < 4; j++)
                    acc[i][j] = fmaf(a[i], w[j], acc[i][j]);
        }
        __syncthreads();
    }

    float scale[4] = {1.f, 1.f, 1.f, 1.f};
    if (z) {
        #pragma unroll
        for (int i = 0; i < 4; i++) {
            int c = g_cnt[n0 + tn * 4 + i];
            scale[i] = 1.0f / ((c > 0) ? (float)c : 1.0f);
        }
    }
    #pragma unroll
    for (int j = 0; j < 4; j++) {
        int h = h0 + th * 4 + j;
        float bb = z ? b1[h] : 0.f;
        float4 v = make_float4(acc[0][j] * scale[0] + bb,
                               acc[1][j] * scale[1] + bb,
                               acc[2][j] * scale[2] + bb,
                               acc[3][j] * scale[3] + bb);
        *(float4*)&outT[h * N_ + n0 + tn * 4] = v;
    }
    pdl_trigger();
}

// ---------------- stage 3: main N x M x H contraction (h-split) ----------
// grid (H/64, M/64, N/64) = 1024 blocks, 128 threads, all co-resident.
// Exact R3 inner loop (29.0us). PDL wait before touching gemm outputs.
__global__ __launch_bounds__(128, 7) void k_main(const float* __restrict__ W2,
                                                 float* __restrict__ out) {
    __shared__ __align__(16) float hx_s[32][64];
    __shared__ __align__(16) float heb_s[32][64];
    __shared__ float w2_s[64];

    int hb = blockIdx.x * 64;
    int m0 = blockIdx.y * 64;
    int n0 = blockIdx.z * 64;
    int tid = threadIdx.x;
    int tn  = tid & 15;   // n base = tn*4
    int tm  = tid >> 4;   // m base = tm*8

    u64 acc[4][4];        // [ni][mpair]
    #pragma unroll
    for (int i = 0; i < 4; i++)
        #pragma unroll
        for (int p = 0; p < 4; p++)
            acc[i][p] = 0ull;

    if (tid < 64) w2_s[tid] = W2[hb + tid];   // input, independent of gemm

    pdl_wait();

    int cg = tid & 15;    // float4 column group for loads
    int r0 = tid >> 4;    // row base for loads (0..7)

    for (int sc = 0; sc < 2; sc++) {
        int hbase = hb + sc * 32;
        #pragma unroll
        for (int k = 0; k < 4; k++) {
            int hh = k * 8 + r0;
            *(float4*)&hx_s[hh][cg * 4]  = *(const float4*)&g_hxT[(hbase + hh) * N_ + n0 + cg * 4];
            *(float4*)&heb_s[hh][cg * 4] = *(const float4*)&g_hebT[(hbase + hh) * M_ + m0 + cg * 4];
        }
        __syncthreads();

        #pragma unroll 4
        for (int hh = 0; hh < 32; hh++) {
            float4 hx4 = *(const float4*)&hx_s[hh][tn * 4];
            ulonglong2 e0 = *(const ulonglong2*)&heb_s[hh][tm * 8];
            ulonglong2 e1 = *(const ulonglong2*)&heb_s[hh][tm * 8 + 4];
            u64 w2p = bcast2(w2_s[sc * 32 + hh]);
            u64 q0 = bcast2(hx4.x);
            u64 q1 = bcast2(hx4.y);
            u64 q2 = bcast2(hx4.z);
            u64 q3 = bcast2(hx4.w);

            relu_fma2(acc[0][0], e0.x, q0, w2p);
            relu_fma2(acc[0][1], e0.y, q0, w2p);
            relu_fma2(acc[0][2], e1.x, q0, w2p);
            relu_fma2(acc[0][3], e1.y, q0, w2p);

            relu_fma2(acc[1][0], e0.x, q1, w2p);
            relu_fma2(acc[1][1], e0.y, q1, w2p);
            relu_fma2(acc[1][2], e1.x, q1, w2p);
            relu_fma2(acc[1][3], e1.y, q1, w2p);

            relu_fma2(acc[2][0], e0.x, q2, w2p);
            relu_fma2(acc[2][1], e0.y, q2, w2p);
            relu_fma2(acc[2][2], e1.x, q2, w2p);
            relu_fma2(acc[2][3], e1.y, q2, w2p);

            relu_fma2(acc[3][0], e0.x, q3, w2p);
            relu_fma2(acc[3][1], e0.y, q3, w2p);
            relu_fma2(acc[3][2], e1.x, q3, w2p);
            relu_fma2(acc[3][3], e1.y, q3, w2p);
        }
        __syncthreads();
    }

    // epilogue: vector-RED partial logits into out[n][m]
    #pragma unroll
    for (int i = 0; i < 4; i++) {
        int n = n0 + tn * 4 + i;
        float2 a = unpack2(acc[i][0]);
        float2 b = unpack2(acc[i][1]);
        float2 c = unpack2(acc[i][2]);
        float2 d = unpack2(acc[i][3]);
        float* dst = &out[n * M_ + m0 + tm * 8];
        asm volatile("red.global.add.v4.f32 [%0], {%1, %2, %3, %4};"
                     :: "l"(dst), "f"(a.x), "f"(a.y), "f"(b.x), "f"(b.y) : "memory");
        asm volatile("red.global.add.v4.f32 [%0], {%1, %2, %3, %4};"
                     :: "l"(dst + 4), "f"(c.x), "f"(c.y), "f"(d.x), "f"(d.y) : "memory");
    }
    pdl_trigger();
}

// ---------------- stage 4: sigmoid epilogue + re-zero scratch ------------
// Also restores g_sum/g_cnt to zero for the next invocation (gemm already
// consumed them; independent of k_main, so done before the PDL wait).
__global__ __launch_bounds__(256) void k_sig(float* __restrict__ out,
                                             const float* __restrict__ b2p) {
    int i = blockIdx.x * blockDim.x + threadIdx.x;
    if (i < (M_ * D_) / 4) ((float4*)g_sum)[i] = make_float4(0.f, 0.f, 0.f, 0.f);
    if (i < M_) g_cnt[i] = 0;
    float b2 = b2p[0];
    pdl_wait();
    float4 v = ((float4*)out)[i];
    v.x = sigmoidf_fast(v.x + b2);
    v.y = sigmoidf_fast(v.y + b2);
    v.z = sigmoidf_fast(v.z + b2);
    v.w = sigmoidf_fast(v.w + b2);
    ((float4*)out)[i] = v;
}

// ---------------- launch ----------------
static void launch_pdl(void* fn, dim3 grid, dim3 block, void** args) {
    cudaLaunchConfig_t cfg = {};
    cfg.gridDim = grid;
    cfg.blockDim = block;
    cfg.stream = 0;
    cudaLaunchAttribute attr[1];
    attr[0].id = cudaLaunchAttributeProgrammaticStreamSerialization;
    attr[0].val.programmaticStreamSerializationAllowed = 1;
    cfg.attrs = attr;
    cfg.numAttrs = 1;
    cudaLaunchKernelExC(&cfg, fn, args);
}

extern "C" void kernel_launch(void* const* d_in, const int* in_sizes, int n_in,
                              void* d_out, int out_size) {
    const float* X  = (const float*)d_in[0];
    const int*   V  = (const int*)d_in[1];
    const int*   E  = (const int*)d_in[2];
    const float* W1 = (const float*)d_in[3];
    const float* b1 = (const float*)d_in[4];
    const float* W2 = (const float*)d_in[5];
    const float* b2 = (const float*)d_in[6];
    float* out = (float*)d_out;

    // stage 1: plain launch (first node; depends only on prior graph replay)
    k_scatter<<<1024 + NNZ_ / 8, 256>>>(X, V, E, out);

    // stages 2-4: PDL dependents
    {
        void* args[] = {(void*)&X, (void*)&W1, (void*)&b1};
        launch_pdl((void*)k_gemm, dim3(N_ / 64, H_ / 64, 2), dim3(256), args);
    }
    {
        void* args[] = {(void*)&W2, (void*)&out};
        launch_pdl((void*)k_main, dim3(H_ / 64, M_ / 64, N_ / 64), dim3(128), args);
    }
    {
        void* args[] = {(void*)&out, (void*)&b2};
        launch_pdl((void*)k_sig, dim3(1024), dim3(256), args);
    }
}

// round 8
// speedup vs baseline: 1.1702x; 1.0883x over previous
#include <cuda_runtime.h>

#define N_    1024
#define M_    1024
#define D_    128
#define NNZ_  32768
#define H_    256

typedef unsigned long long u64;

// ---------------- device scratch (no allocations allowed) ----------------
// Zero-initialized at module load; k_sig restores the zero state for
// g_sum / g_cnt after each invocation, so every call sees zeroed scratch.
__device__ int   g_cnt[M_];
__device__ __align__(16) float g_sum[M_ * D_];     // raw scatter sums [m][d]
__device__ __align__(16) float g_hxT[H_ * N_];     // [h][n]
__device__ __align__(16) float g_hebT[H_ * M_];    // [h][m]  (includes /cnt and +b1)

// ---------------- small helpers ----------------
__device__ __forceinline__ u64 bcast2(float v) {
    u64 r;
    asm("mov.b64 %0, {%1, %1};" : "=l"(r) : "f"(v));
    return r;
}

__device__ __forceinline__ float2 unpack2(u64 v) {
    float lo, hi;
    asm("mov.b64 {%0, %1}, %2;" : "=f"(lo), "=f"(hi) : "l"(v));
    return make_float2(lo, hi);
}

// acc2 += relu(a2 + b2) * w2   (packed f32x2; relu on the scalar halves)
__device__ __forceinline__ void relu_fma2(u64 &acc, u64 a, u64 b, u64 w) {
    asm("{\n\t"
        ".reg .b64 t;\n\t"
        ".reg .f32 lo, hi;\n\t"
        "add.rn.f32x2 t, %1, %2;\n\t"
        "mov.b64 {lo, hi}, t;\n\t"
        "max.f32 lo, lo, 0f00000000;\n\t"
        "max.f32 hi, hi, 0f00000000;\n\t"
        "mov.b64 t, {lo, hi};\n\t"
        "fma.rn.f32x2 %0, t, %3, %0;\n\t"
        "}"
        : "+l"(acc) : "l"(a), "l"(b), "l"(w));
}

__device__ __forceinline__ float sigmoidf_fast(float x) {
    return 1.0f / (1.0f + __expf(-x));
}

// ---------------- stage 1: scatter (+ init d_out to b2 in extra blocks) --
// blocks [0,1024): out[..] = b2 (REDs then accumulate logits onto b2).
// blocks [1024,5120): one warp per edge, vector-RED into g_sum.
__global__ __launch_bounds__(256) void k_scatter(const float* __restrict__ X,
                                                 const int* __restrict__ V,
                                                 const int* __restrict__ E,
                                                 const float* __restrict__ b2p,
                                                 float* __restrict__ out) {
    int bx = blockIdx.x;
    if (bx < 1024) {
        float b = b2p[0];
        int i = bx * 256 + threadIdx.x;
        ((float4*)out)[i] = make_float4(b, b, b, b);
        return;
    }
    int edge = (bx - 1024) * 8 + (threadIdx.x >> 5);
    int lane = threadIdx.x & 31;
    int e = E[edge];
    int v = V[edge];
    float4 x = *(const float4*)&X[v * D_ + lane * 4];
    float* dst = &g_sum[e * D_ + lane * 4];
    asm volatile("red.global.add.v4.f32 [%0], {%1, %2, %3, %4};"
                 :: "l"(dst), "f"(x.x), "f"(x.y), "f"(x.z), "f"(x.w) : "memory");
    if (lane == 0) atomicAdd(&g_cnt[e], 1);
}

// ---------------- stage 2: the two small GEMMs (fused, transposed output) --
// z==0: outT = (X @ W1[:D]).T                       -> g_hxT[h][n]
// z==1: outT = ((g_sum @ W1[D:]) * rcp_cnt).T + b1  -> g_hebT[h][m]
__global__ __launch_bounds__(256) void k_gemm(const float* __restrict__ X,
                                              const float* __restrict__ W1,
                                              const float* __restrict__ b1) {
    int z = blockIdx.z;
    const float* A    = z ? g_sum  : X;
    float*       outT = z ? g_hebT : g_hxT;
    int dof = z ? D_ : 0;

    int n0 = blockIdx.x * 64;
    int h0 = blockIdx.y * 64;

    __shared__ float As[16][65];   // [dk][n]
    __shared__ float Ws[16][64];   // [dk][h]

    int tid = threadIdx.x;
    int tn  = tid & 15;
    int th  = tid >> 4;

    float acc[4][4];
    #pragma unroll
    for (int i = 0; i < 4; i++)
        #pragma unroll
        for (int j = 0; j < 4; j++)
            acc[i][j] = 0.f;

    for (int d0 = 0; d0 < D_; d0 += 16) {
        #pragma unroll
        for (int r = 0; r < 4; r++) {
            int i  = r * 256 + tid;
            int dk = i & 15;
            int nl = i >> 4;
            As[dk][nl] = A[(n0 + nl) * D_ + d0 + dk];
        }
        #pragma unroll
        for (int r = 0; r < 4; r++) {
            int i  = r * 256 + tid;
            int hh = i & 63;
            int dk = i >> 6;
            Ws[dk][hh] = W1[(dof + d0 + dk) * H_ + h0 + hh];
        }
        __syncthreads();
        #pragma unroll
        for (int dk = 0; dk < 16; dk++) {
            float a[4], w[4];
            #pragma unroll
            for (int i = 0; i < 4; i++) a[i] = As[dk][tn * 4 + i];
            #pragma unroll
            for (int j = 0; j < 4; j++) w[j] = Ws[dk][th * 4 + j];
            #pragma unroll
            for (int i = 0; i < 4; i++)
                #pragma unroll
                for (int j = 0; j < 4; j++)
                    acc[i][j] = fmaf(a[i], w[j], acc[i][j]);
        }
        __syncthreads();
    }

    float scale[4] = {1.f, 1.f, 1.f, 1.f};
    if (z) {
        #pragma unroll
        for (int i = 0; i < 4; i++) {
            int c = g_cnt[n0 + tn * 4 + i];
            scale[i] = 1.0f / ((c > 0) ? (float)c : 1.0f);
        }
    }
    #pragma unroll
    for (int j = 0; j < 4; j++) {
        int h = h0 + th * 4 + j;
        float bb = z ? b1[h] : 0.f;
        float4 v = make_float4(acc[0][j] * scale[0] + bb,
                               acc[1][j] * scale[1] + bb,
                               acc[2][j] * scale[2] + bb,
                               acc[3][j] * scale[3] + bb);
        *(float4*)&outT[h * N_ + n0 + tn * 4] = v;
    }
}

// ---------------- stage 3: main N x M x H contraction (h-split) ----------
// grid (H/64, M/64, N/64) = 1024 blocks, 128 threads, all co-resident.
// Exact R3 inner loop (known 29.0us).
__global__ __launch_bounds__(128, 7) void k_main(const float* __restrict__ W2,
                                                 float* __restrict__ out) {
    __shared__ __align__(16) float hx_s[32][64];
    __shared__ __align__(16) float heb_s[32][64];
    __shared__ float w2_s[64];

    int hb = blockIdx.x * 64;
    int m0 = blockIdx.y * 64;
    int n0 = blockIdx.z * 64;
    int tid = threadIdx.x;
    int tn  = tid & 15;   // n base = tn*4
    int tm  = tid >> 4;   // m base = tm*8

    u64 acc[4][4];        // [ni][mpair]
    #pragma unroll
    for (int i = 0; i < 4; i++)
        #pragma unroll
        for (int p = 0; p < 4; p++)
            acc[i][p] = 0ull;

    if (tid < 64) w2_s[tid] = W2[hb + tid];

    int cg = tid & 15;    // float4 column group for loads
    int r0 = tid >> 4;    // row base for loads (0..7)

    for (int sc = 0; sc < 2; sc++) {
        int hbase = hb + sc * 32;
        #pragma unroll
        for (int k = 0; k < 4; k++) {
            int hh = k * 8 + r0;
            *(float4*)&hx_s[hh][cg * 4]  = *(const float4*)&g_hxT[(hbase + hh) * N_ + n0 + cg * 4];
            *(float4*)&heb_s[hh][cg * 4] = *(const float4*)&g_hebT[(hbase + hh) * M_ + m0 + cg * 4];
        }
        __syncthreads();

        #pragma unroll 4
        for (int hh = 0; hh < 32; hh++) {
            float4 hx4 = *(const float4*)&hx_s[hh][tn * 4];
            ulonglong2 e0 = *(const ulonglong2*)&heb_s[hh][tm * 8];
            ulonglong2 e1 = *(const ulonglong2*)&heb_s[hh][tm * 8 + 4];
            u64 w2p = bcast2(w2_s[sc * 32 + hh]);
            u64 q0 = bcast2(hx4.x);
            u64 q1 = bcast2(hx4.y);
            u64 q2 = bcast2(hx4.z);
            u64 q3 = bcast2(hx4.w);

            relu_fma2(acc[0][0], e0.x, q0, w2p);
            relu_fma2(acc[0][1], e0.y, q0, w2p);
            relu_fma2(acc[0][2], e1.x, q0, w2p);
            relu_fma2(acc[0][3], e1.y, q0, w2p);

            relu_fma2(acc[1][0], e0.x, q1, w2p);
            relu_fma2(acc[1][1], e0.y, q1, w2p);
            relu_fma2(acc[1][2], e1.x, q1, w2p);
            relu_fma2(acc[1][3], e1.y, q1, w2p);

            relu_fma2(acc[2][0], e0.x, q2, w2p);
            relu_fma2(acc[2][1], e0.y, q2, w2p);
            relu_fma2(acc[2][2], e1.x, q2, w2p);
            relu_fma2(acc[2][3], e1.y, q2, w2p);

            relu_fma2(acc[3][0], e0.x, q3, w2p);
            relu_fma2(acc[3][1], e0.y, q3, w2p);
            relu_fma2(acc[3][2], e1.x, q3, w2p);
            relu_fma2(acc[3][3], e1.y, q3, w2p);
        }
        __syncthreads();
    }

    // epilogue: vector-RED partial logits into out[n][m] (on top of b2 init)
    #pragma unroll
    for (int i = 0; i < 4; i++) {
        int n = n0 + tn * 4 + i;
        float2 a = unpack2(acc[i][0]);
        float2 b = unpack2(acc[i][1]);
        float2 c = unpack2(acc[i][2]);
        float2 d = unpack2(acc[i][3]);
        float* dst = &out[n * M_ + m0 + tm * 8];
        asm volatile("red.global.add.v4.f32 [%0], {%1, %2, %3, %4};"
                     :: "l"(dst), "f"(a.x), "f"(a.y), "f"(b.x), "f"(b.y) : "memory");
        asm volatile("red.global.add.v4.f32 [%0], {%1, %2, %3, %4};"
                     :: "l"(dst + 4), "f"(c.x), "f"(c.y), "f"(d.x), "f"(d.y) : "memory");
    }
}

// ---------------- stage 4: sigmoid epilogue (ILP=4) + re-zero scratch ----
// 256 blocks x 256 threads; each thread: 4 coalesced float4s in flight.
// b2 already folded into the accumulated logits.
__global__ __launch_bounds__(256) void k_sig(float* __restrict__ out) {
    int tid  = threadIdx.x;
    int base = blockIdx.x * 1024 + tid;     // float4 index
    float4* o4 = (float4*)out;

    float4 v[4];
    #pragma unroll
    for (int k = 0; k < 4; k++) v[k] = o4[base + k * 256];

    // restore scratch zero-state for the next invocation (overlaps MUFU work)
    int i = blockIdx.x * 256 + tid;
    if (i < (M_ * D_) / 4) ((float4*)g_sum)[i] = make_float4(0.f, 0.f, 0.f, 0.f);
    if (i < M_) g_cnt[i] = 0;

    #pragma unroll
    for (int k = 0; k < 4; k++) {
        v[k].x = sigmoidf_fast(v[k].x);
        v[k].y = sigmoidf_fast(v[k].y);
        v[k].z = sigmoidf_fast(v[k].z);
        v[k].w = sigmoidf_fast(v[k].w);
    }
    #pragma unroll
    for (int k = 0; k < 4; k++) o4[base + k * 256] = v[k];
}

// ---------------- launch ----------------
extern "C" void kernel_launch(void* const* d_in, const int* in_sizes, int n_in,
                              void* d_out, int out_size) {
    const float* X  = (const float*)d_in[0];
    const int*   V  = (const int*)d_in[1];
    const int*   E  = (const int*)d_in[2];
    const float* W1 = (const float*)d_in[3];
    const float* b1 = (const float*)d_in[4];
    const float* W2 = (const float*)d_in[5];
    const float* b2 = (const float*)d_in[6];
    float* out = (float*)d_out;

    k_scatter<<<1024 + NNZ_ / 8, 256>>>(X, V, E, b2, out);
    k_gemm<<<dim3(N_ / 64, H_ / 64, 2), 256>>>(X, W1, b1);
    k_main<<<dim3(H_ / 64, M_ / 64, N_ / 64), 128>>>(W2, out);
    k_sig<<<256, 256>>>(out);
}